// round 5
// baseline (speedup 1.0000x reference)
#include <cuda_runtime.h>
#include <cstdint>

// Problem constants (16 clips of 10 s @ 48 kHz)
#define N_SAMP  480000
#define NP1     480001          // envelope length per row
#define WIN     240             // 5 ms box filter
#define EPSF    1e-6f

// Tiling
#define NTHR    256
#define EPT     16              // d elements / prefix slots per thread
#define T_OUT   3840            // envelope outputs per block
#define L_DV    (T_OUT + WIN - 1)   // 4079 valid d elements per tile
#define PPAD    4368            // padded prefix array (4096 + 16*16 pad + slack)
#define MAXB    16

// Scratch (zero-initialized at load; reset by last block each run)
struct RowAcc { double s1, s2; int m; int pad[3]; };
__device__ RowAcc       g_acc[MAXB];
__device__ unsigned int g_count;

struct SMF {
    float Pp[PPAD];             // padded exclusive prefix of |diff|, y_pred
    float Pt[PPAD];             // padded exclusive prefix of |diff|, y_true
    float wsP[8], wsT[8];
    float r1[8], r2[8], r3[8];
};

// Compute thread-local diffs d[m], m in [m0, m0+16), d[m] = |x[id]-x[id-1]|,
// id = j0-120+m. Fills run[] (inclusive local prefix), returns local total.
template<bool INTERIOR>
__device__ __forceinline__ float diffs(const float* __restrict__ x, int j0,
                                       int m0, int lane, float run[EPT])
{
    if (INTERIOR) {
        // 16 contiguous x values, 16B-aligned: j0-120+m0 = j0-120+16t (mult of 4)
        const float4* p4 = reinterpret_cast<const float4*>(x + (j0 - 120 + m0));
        float4 A0 = p4[0], A1 = p4[1], A2 = p4[2], A3 = p4[3];
        float e[EPT] = { A0.x, A0.y, A0.z, A0.w,  A1.x, A1.y, A1.z, A1.w,
                         A2.x, A2.y, A2.z, A2.w,  A3.x, A3.y, A3.z, A3.w };
        // preceding element: neighbor's last lane value (scalar LDG at lane 0)
        float xm1 = __shfl_up_sync(0xffffffffu, A3.w, 1);
        if (lane == 0) xm1 = x[j0 - 121 + m0];

        float s = 0.f, prev = xm1;
        #pragma unroll
        for (int c = 0; c < EPT; c++) {
            s += fabsf(e[c] - prev);
            prev = e[c];
            run[c] = s;
        }
        return s;
    } else {
        float s = 0.f, prev;
        {
            int i = j0 - 121 + m0;
            prev = (i >= 0 && i < N_SAMP) ? x[i] : 0.f;
        }
        #pragma unroll
        for (int c = 0; c < EPT; c++) {
            int i = j0 - 120 + m0 + c;   // x index of current elem == d index
            float cur = (i >= 0 && i < N_SAMP) ? x[i] : 0.f;
            bool ok = (i >= 1) && (i < N_SAMP) && (m0 + c < L_DV);
            s += ok ? fabsf(cur - prev) : 0.f;
            prev = cur;
            run[c] = s;
        }
        return s;
    }
}

__global__ __launch_bounds__(NTHR)
void k_fused(const float* __restrict__ y_pred, const float* __restrict__ y_true,
             float* __restrict__ out, int B, double invcnt)
{
    __shared__ SMF sm;
    const int t = threadIdx.x, lane = t & 31, wid = t >> 5;
    const int row = blockIdx.y;
    const int j0  = blockIdx.x * T_OUT;
    const int m0  = t * EPT;
    const float* xp = y_pred + (size_t)row * N_SAMP;
    const float* xt = y_true + (size_t)row * N_SAMP;

    // interior: all thread loads in-bounds AND all 3840 outputs valid AND
    // all needed d's real (no reference-padding zeros inside the window).
    const bool interior = (blockIdx.x >= 1) && (blockIdx.x + 2 < gridDim.x);

    float runP[EPT], runT[EPT];
    float sP, sT;
    if (interior) {
        sP = diffs<true >(xp, j0, m0, lane, runP);
        sT = diffs<true >(xt, j0, m0, lane, runT);
    } else {
        sP = diffs<false>(xp, j0, m0, lane, runP);
        sT = diffs<false>(xt, j0, m0, lane, runT);
    }

    // ---- Warp inclusive scans of thread totals (two independent chains) ----
    float vP = sP, vT = sT;
    #pragma unroll
    for (int off = 1; off < 32; off <<= 1) {
        float uP = __shfl_up_sync(0xffffffffu, vP, off);
        float uT = __shfl_up_sync(0xffffffffu, vT, off);
        if (lane >= off) { vP += uP; vT += uT; }
    }
    if (lane == 31) { sm.wsP[wid] = vP; sm.wsT[wid] = vT; }
    __syncthreads();

    float baseP = vP - sP, baseT = vT - sT;      // exclusive base for m0
    #pragma unroll
    for (int w = 0; w < 7; w++)
        if (w < wid) { baseP += sm.wsP[w]; baseT += sm.wsT[w]; }

    // ---- Write padded exclusive prefix: P[k=16t+c] at idx 17t+c ----
    // byte stride 68 per thread -> bank 17*lane mod 32, conflict-free.
    const int kp = 17 * t;
    sm.Pp[kp] = baseP;
    sm.Pt[kp] = baseT;
    #pragma unroll
    for (int c = 1; c < EPT; c++) {
        sm.Pp[kp + c] = baseP + runP[c - 1];
        sm.Pt[kp + c] = baseT + runT[c - 1];
    }
    __syncthreads();

    // ---- Envelopes + partial sums; P[jj] from registers, P[jj+240] from smem
    float s1 = 0.f, s2 = 0.f, mx = 0.f;
    if (t < T_OUT / EPT) {                       // t < 240
        const float inv = 1.f / (float)WIN;
        const int kq = 17 * t + 255;             // padded idx of k = 16t+240
        #pragma unroll
        for (int c = 0; c < EPT; c++) {
            int jj = m0 + c;
            if (interior || (j0 + jj < NP1)) {
                float P0 = baseP + (c ? runP[c - 1] : 0.f);
                float T0 = baseT + (c ? runT[c - 1] : 0.f);
                float Ep = (sm.Pp[kq + c] - P0) * inv;
                float Et = (sm.Pt[kq + c] - T0) * inv;
                float df = fabsf(__logf(Ep + EPSF) - __logf(Et + EPSF));
                s1 += df; s2 += df * Et; mx = fmaxf(mx, Et);
            }
        }
    }

    // ---- Block reduction of (S1, S2, M) ----
    #pragma unroll
    for (int off = 16; off > 0; off >>= 1) {
        s1 += __shfl_down_sync(0xffffffffu, s1, off);
        s2 += __shfl_down_sync(0xffffffffu, s2, off);
        mx  = fmaxf(mx, __shfl_down_sync(0xffffffffu, mx, off));
    }
    if (lane == 0) { sm.r1[wid] = s1; sm.r2[wid] = s2; sm.r3[wid] = mx; }
    __syncthreads();

    if (t == 0) {
        float a1 = 0.f, a2 = 0.f, am = 0.f;
        #pragma unroll
        for (int w = 0; w < 8; w++) {
            a1 += sm.r1[w]; a2 += sm.r2[w]; am = fmaxf(am, sm.r3[w]);
        }
        atomicAdd(&g_acc[row].s1, (double)a1);
        atomicAdd(&g_acc[row].s2, (double)a2);
        atomicMax(&g_acc[row].m, __float_as_int(am));   // valid: env >= 0
        __threadfence();

        unsigned int total = gridDim.x * gridDim.y;
        unsigned int old = atomicAdd(&g_count, 1u);
        if (old == total - 1u) {
            // Last block: finalize, write output, reset scratch for next replay.
            __threadfence();
            double tot = 0.0;
            for (int r = 0; r < B; r++) {
                volatile double* p1 = &g_acc[r].s1;
                volatile double* p2 = &g_acc[r].s2;
                volatile int*    pm = &g_acc[r].m;
                double S1 = *p1;
                double S2 = *p2;
                float  M  = __int_as_float(*pm);
                tot += 0.2 * S1 + 0.8 * S2 / ((double)M + (double)EPSF);
                g_acc[r].s1 = 0.0; g_acc[r].s2 = 0.0; g_acc[r].m = 0;
            }
            out[0] = (float)(tot * invcnt);
            g_count = 0u;
            __threadfence();
        }
    }
}

extern "C" void kernel_launch(void* const* d_in, const int* in_sizes, int n_in,
                              void* d_out, int out_size)
{
    const float* y_pred = (const float*)d_in[0];
    const float* y_true = (const float*)d_in[1];
    float* out = (float*)d_out;

    const int B     = in_sizes[0] / N_SAMP;              // 16
    const int tiles = (NP1 + T_OUT - 1) / T_OUT;         // 126

    k_fused<<<dim3(tiles, B), NTHR>>>(y_pred, y_true, out, B,
                                      1.0 / ((double)B * (double)NP1));
}

// round 6
// speedup vs baseline: 1.0918x; 1.0918x over previous
#include <cuda_runtime.h>
#include <cstdint>

// Problem constants (16 clips of 10 s @ 48 kHz)
#define N_SAMP  480000
#define NP1     480001          // envelope length per row
#define WIN     240             // 5 ms box filter
#define EPSF    1e-6f

// Tiling
#define NTHR    256
#define EPT     16              // d elements / prefix slots per thread
#define T_OUT   3840            // envelope outputs per block (240 env threads * 16)
#define L_DV    (T_OUT + WIN - 1)   // 4079 valid d elements per tile
#define PPAD    4352            // padded prefix array (17*255+15 = 4350 max idx)
#define MAXB    16

// Scratch (zero-initialized at load; reset by last block each run)
struct RowAcc { double s1, s2; int m; int pad[3]; };
__device__ RowAcc       g_acc[MAXB];
__device__ unsigned int g_count;

struct SMF {
    float  Pp[PPAD];            // padded exclusive prefix of |diff|, y_pred
    float  Pt[PPAD];            // padded exclusive prefix of |diff|, y_true
    float  wsP[8], wsT[8];
    float  r1[8], r2[8], r3[8];
    double fin[MAXB];
    int    flag;
};

// Thread-local diffs d[m], m in [m0, m0+16), d[m] = |x[id]-x[id-1]|, id = j0-120+m.
template<bool INTERIOR>
__device__ __forceinline__ float diffs(const float* __restrict__ x, int j0,
                                       int m0, int lane, float run[EPT])
{
    if (INTERIOR) {
        // 16 contiguous x values, 16B-aligned (j0-120+16t is a multiple of 4)
        const float4* p4 = reinterpret_cast<const float4*>(x + (j0 - 120 + m0));
        float4 A0 = p4[0], A1 = p4[1], A2 = p4[2], A3 = p4[3];
        float e[EPT] = { A0.x, A0.y, A0.z, A0.w,  A1.x, A1.y, A1.z, A1.w,
                         A2.x, A2.y, A2.z, A2.w,  A3.x, A3.y, A3.z, A3.w };
        float xm1 = __shfl_up_sync(0xffffffffu, A3.w, 1);
        if (lane == 0) xm1 = x[j0 - 121 + m0];

        float s = 0.f, prev = xm1;
        #pragma unroll
        for (int c = 0; c < EPT; c++) {
            s += fabsf(e[c] - prev);
            prev = e[c];
            run[c] = s;
        }
        return s;
    } else {
        float s = 0.f, prev;
        {
            int i = j0 - 121 + m0;
            prev = (i >= 0 && i < N_SAMP) ? x[i] : 0.f;
        }
        #pragma unroll
        for (int c = 0; c < EPT; c++) {
            int i = j0 - 120 + m0 + c;   // x index of current elem == d index
            float cur = (i >= 0 && i < N_SAMP) ? x[i] : 0.f;
            bool ok = (i >= 1) && (i < N_SAMP) && (m0 + c < L_DV);
            s += ok ? fabsf(cur - prev) : 0.f;
            prev = cur;
            run[c] = s;
        }
        return s;
    }
}

// Build the padded exclusive prefix for one signal. Contains ONE __syncthreads.
// run[] lives only inside this function -> low register pressure.
template<bool INTERIOR>
__device__ __forceinline__ void build_prefix(const float* __restrict__ x, int j0,
                                             int m0, int t, int lane, int wid,
                                             float* __restrict__ Ps,
                                             float* __restrict__ ws)
{
    float run[EPT];
    float s = diffs<INTERIOR>(x, j0, m0, lane, run);

    float v = s;
    #pragma unroll
    for (int off = 1; off < 32; off <<= 1) {
        float u = __shfl_up_sync(0xffffffffu, v, off);
        if (lane >= off) v += u;
    }
    if (lane == 31) ws[wid] = v;
    __syncthreads();

    float base = v - s;                 // exclusive base within warp
    #pragma unroll
    for (int w = 0; w < 7; w++)
        if (w < wid) base += ws[w];

    // P[k=16t+c] at padded idx 17t+c: bank 17*lane mod 32, conflict-free.
    const int kp = 17 * t;
    Ps[kp] = base;
    #pragma unroll
    for (int c = 1; c < EPT; c++) Ps[kp + c] = base + run[c - 1];
}

__global__ __launch_bounds__(NTHR, 6)
void k_fused(const float* __restrict__ y_pred, const float* __restrict__ y_true,
             float* __restrict__ out, int B, double invcnt)
{
    __shared__ SMF sm;
    const int t = threadIdx.x, lane = t & 31, wid = t >> 5;
    const int row = blockIdx.y;
    const int j0  = blockIdx.x * T_OUT;
    const int m0  = t * EPT;
    const float* xp = y_pred + (size_t)row * N_SAMP;
    const float* xt = y_true + (size_t)row * N_SAMP;

    const bool interior = (blockIdx.x >= 1) && (blockIdx.x + 2 < gridDim.x);

    if (interior) {
        build_prefix<true >(xt, j0, m0, t, lane, wid, sm.Pt, sm.wsT);
        build_prefix<true >(xp, j0, m0, t, lane, wid, sm.Pp, sm.wsP);
    } else {
        build_prefix<false>(xt, j0, m0, t, lane, wid, sm.Pt, sm.wsT);
        build_prefix<false>(xp, j0, m0, t, lane, wid, sm.Pp, sm.wsP);
    }
    __syncthreads();

    // ---- Envelopes + partial sums; all P values from conflict-free smem ----
    float s1 = 0.f, s2 = 0.f, mx = 0.f;
    if (t < T_OUT / EPT) {                       // t < 240
        const float inv = 1.f / (float)WIN;
        const int kp = 17 * t;                   // padded idx of k = 16t
        const int kq = kp + 255;                 // padded idx of k = 16t+240
        #pragma unroll
        for (int c = 0; c < EPT; c++) {
            if (interior || (j0 + m0 + c < NP1)) {
                float Ep = (sm.Pp[kq + c] - sm.Pp[kp + c]) * inv;
                float Et = (sm.Pt[kq + c] - sm.Pt[kp + c]) * inv;
                float df = fabsf(__logf(Ep + EPSF) - __logf(Et + EPSF));
                s1 += df; s2 += df * Et; mx = fmaxf(mx, Et);
            }
        }
    }

    // ---- Block reduction of (S1, S2, M) ----
    #pragma unroll
    for (int off = 16; off > 0; off >>= 1) {
        s1 += __shfl_down_sync(0xffffffffu, s1, off);
        s2 += __shfl_down_sync(0xffffffffu, s2, off);
        mx  = fmaxf(mx, __shfl_down_sync(0xffffffffu, mx, off));
    }
    if (lane == 0) { sm.r1[wid] = s1; sm.r2[wid] = s2; sm.r3[wid] = mx; }
    __syncthreads();

    if (t == 0) {
        float a1 = 0.f, a2 = 0.f, am = 0.f;
        #pragma unroll
        for (int w = 0; w < 8; w++) {
            a1 += sm.r1[w]; a2 += sm.r2[w]; am = fmaxf(am, sm.r3[w]);
        }
        atomicAdd(&g_acc[row].s1, (double)a1);
        atomicAdd(&g_acc[row].s2, (double)a2);
        atomicMax(&g_acc[row].m, __float_as_int(am));   // valid: env >= 0
        __threadfence();

        unsigned int total = gridDim.x * gridDim.y;
        unsigned int old = atomicAdd(&g_count, 1u);
        sm.flag = (old == total - 1u) ? 1 : 0;
    }
    __syncthreads();

    if (sm.flag) {
        // Last block in the grid: finalize in parallel, reset scratch for replay.
        __threadfence();
        if (t < B) {
            volatile double* p1 = &g_acc[t].s1;
            volatile double* p2 = &g_acc[t].s2;
            volatile int*    pm = &g_acc[t].m;
            double S1 = *p1;
            double S2 = *p2;
            float  M  = __int_as_float(*pm);
            sm.fin[t] = 0.2 * S1 + 0.8 * S2 / ((double)M + (double)EPSF);
            g_acc[t].s1 = 0.0; g_acc[t].s2 = 0.0; g_acc[t].m = 0;
        }
        __syncthreads();
        if (t == 0) {
            double tot = 0.0;
            for (int r = 0; r < B; r++) tot += sm.fin[r];
            out[0] = (float)(tot * invcnt);
            g_count = 0u;
            __threadfence();
        }
    }
}

extern "C" void kernel_launch(void* const* d_in, const int* in_sizes, int n_in,
                              void* d_out, int out_size)
{
    const float* y_pred = (const float*)d_in[0];
    const float* y_true = (const float*)d_in[1];
    float* out = (float*)d_out;

    const int B     = in_sizes[0] / N_SAMP;              // 16
    const int tiles = (NP1 + T_OUT - 1) / T_OUT;         // 126

    k_fused<<<dim3(tiles, B), NTHR>>>(y_pred, y_true, out, B,
                                      1.0 / ((double)B * (double)NP1));
}